// round 14
// baseline (speedup 1.0000x reference)
#include <cuda_runtime.h>
#include <cstdint>

#define DEV_INLINE __device__ __forceinline__
typedef unsigned long long ull;

// ---------------- scratch (device globals; no allocations allowed) ----------
__device__ float g_c1[16 * 1024 * 256];            // after conv1 + frame grouping
__device__ float g_c2[16 * 1024 * 256];            // after conv2
__device__ float g_c3[16 * 4096 * 256];            // after tconv
__device__ float g_gx[(size_t)16 * 8 * 4096 * 96]; // gates_x, GRU-CTA-sliced layout
__device__ float g_w2t[512 * 256];                 // W2 transposed: [kk][o]
__device__ float g_wihT[256 * 768];                // W_ih transposed: [c][g]

// ---------------- packed f32x2 helpers --------------------------------------
DEV_INLINE ull dup2(float x) {
    ull r; asm("mov.b64 %0, {%1, %1};" : "=l"(r) : "f"(x)); return r;
}
DEV_INLINE void fma2(ull& d, ull a, ull b) {
    asm("fma.rn.f32x2 %0, %1, %2, %0;" : "+l"(d) : "l"(a), "l"(b));
}
DEV_INLINE void unpack2(ull v, float& x, float& y) {
    asm("mov.b64 {%0, %1}, %2;" : "=f"(x), "=f"(y) : "l"(v));
}

// ---------------- fast activations (MUFU ex2 + rcp; rel err ~1e-6) ----------
DEV_INLINE float fast_tanh(float x) {
    x = fminf(15.f, fmaxf(-15.f, x));
    float e = __expf(2.f * x);
    return __fdividef(e - 1.f, e + 1.f);
}
DEV_INLINE float fast_sig(float x) {
    x = fminf(30.f, fmaxf(-30.f, x));
    return __fdividef(1.f, 1.f + __expf(-x));
}

// ---------------- cluster helpers (raw DSMEM stores, NO sync machinery) -----
DEV_INLINE uint32_t smem_u32(const void* p) {
    return (uint32_t)__cvta_generic_to_shared(p);
}
DEV_INLINE uint32_t mapa_u32(uint32_t laddr, int rank) {
    uint32_t r;
    asm volatile("mapa.shared::cluster.u32 %0, %1, %2;" : "=r"(r) : "r"(laddr), "r"(rank));
    return r;
}
// plain LSU remote smem store (fire-and-forget, ~215 cyc flight)
DEV_INLINE void st_cluster_b64(uint32_t raddr, ull v) {
    asm volatile("st.shared::cluster.b64 [%0], %1;" :: "r"(raddr), "l"(v) : "memory");
}
// volatile local-smem poll (29-cyc LDS granularity; 8B is single-copy atomic)
DEV_INLINE ull ld_volatile_shared_b64(uint32_t a) {
    ull v;
    asm volatile("ld.volatile.shared.b64 %0, [%1];" : "=l"(v) : "r"(a) : "memory");
    return v;
}
DEV_INLINE void cluster_sync_() {
    asm volatile("barrier.cluster.arrive.aligned;" ::: "memory");
    asm volatile("barrier.cluster.wait.aligned;" ::: "memory");
}

// ============================================================================
// Kernel A: conv1 (k=1 pointwise, 47->64) + tanh + frame grouping (B,1024,256)
// ============================================================================
__global__ __launch_bounds__(256) void conv1_kernel(
    const float* __restrict__ feat, const float* __restrict__ W1,
    const float* __restrict__ b1)
{
    __shared__ float sW[64 * 47];
    __shared__ float sb[64];
    __shared__ float sx[32 * 47];
    const int tid = threadIdx.x;
    const int b = blockIdx.y;
    const int f0 = blockIdx.x * 32;
    for (int i = tid; i < 64 * 47; i += 256) sW[i] = W1[i];
    if (tid < 64) sb[tid] = b1[tid];
    const float* fp = feat + ((size_t)b * 4096 + f0) * 47;
    for (int i = tid; i < 32 * 47; i += 256) sx[i] = fp[i];
    __syncthreads();
#pragma unroll
    for (int r = 0; r < 8; r++) {
        int idx = tid + 256 * r;
        int f = idx >> 6, h = idx & 63;
        float acc = sb[h];
#pragma unroll
        for (int i = 0; i < 47; i++) acc = fmaf(sx[f * 47 + i], sW[h * 47 + i], acc);
        int gf = f0 + f;
        g_c1[((size_t)b * 1024 + (gf >> 2)) * 256 + ((gf & 3) << 6) + h] = fast_tanh(acc);
    }
}

// ============================================================================
// Prep: both weight transposes in ONE kernel.
// ============================================================================
__global__ __launch_bounds__(768) void prep_kernel(
    const float* __restrict__ W2, const float* __restrict__ W_ih)
{
    int blk = blockIdx.x;
    int t = threadIdx.x;
    if (blk < 512) {
        if (t < 256)
            g_w2t[blk * 256 + t] = W2[t * 512 + ((blk & 255) << 1) + (blk >> 8)];
    } else {
        int c = blk - 512;                 // 0..255
        g_wihT[c * 768 + t] = W_ih[t * 256 + c];
    }
}

// ============================================================================
// Shared GEMM skeleton (128x128 tile, BK=16, 256 thr, 8x8 micro, f32x2 FMA)
// ============================================================================
template <int MODE>
__global__ __launch_bounds__(256) void gemm_kernel(
    const float* __restrict__ Bext, const float* __restrict__ bias)
{
    __shared__ float As[16][136];
    __shared__ float Bs[16][128];
    const int tid = threadIdx.x;
    const int tx = tid & 15, ty = tid >> 4;
    const int m0 = blockIdx.x * 128;
    const int n0 = blockIdx.y * 128;
    constexpr int K   = (MODE == 0) ? 512 : 256;
    constexpr int Nld = (MODE == 0) ? 256 : (MODE == 1 ? 1024 : 768);
    const float* Bm = (MODE == 0) ? g_w2t : (MODE == 1 ? Bext : g_wihT);
    const float* Amat = (MODE == 1) ? g_c2 : g_c3;

    ull acc[8][4];
#pragma unroll
    for (int i = 0; i < 8; i++)
#pragma unroll
        for (int j = 0; j < 4; j++) acc[i][j] = 0ULL;

    for (int k0 = 0; k0 < K; k0 += 16) {
#pragma unroll
        for (int it = 0; it < 2; it++) {
            int idx = tid + it * 256;
            int row = idx >> 2;
            int kq = (idx & 3) << 2;
            int m = m0 + row;
            float4 v;
            if (MODE == 0) {
                if (k0 < 256) {
                    if ((m & 1023) != 0)
                        v = *(const float4*)&g_c1[((size_t)m - 1) * 256 + k0 + kq];
                    else
                        v = make_float4(0.f, 0.f, 0.f, 0.f);
                } else {
                    v = *(const float4*)&g_c1[(size_t)m * 256 + (k0 - 256) + kq];
                }
            } else {
                v = *(const float4*)&Amat[(size_t)m * 256 + k0 + kq];
            }
            As[kq + 0][row] = v.x; As[kq + 1][row] = v.y;
            As[kq + 2][row] = v.z; As[kq + 3][row] = v.w;
        }
#pragma unroll
        for (int it = 0; it < 2; it++) {
            int idx = tid + it * 256;
            int kr = idx >> 5;
            int nq = (idx & 31) << 2;
            *(float4*)&Bs[kr][nq] = *(const float4*)&Bm[(size_t)(k0 + kr) * Nld + n0 + nq];
        }
        __syncthreads();
#pragma unroll
        for (int kk = 0; kk < 16; kk++) {
            float4 a0 = *(const float4*)&As[kk][ty * 8];
            float4 a1 = *(const float4*)&As[kk][ty * 8 + 4];
            ulonglong2 bb0 = *(const ulonglong2*)&Bs[kk][tx * 8];
            ulonglong2 bb1 = *(const ulonglong2*)&Bs[kk][tx * 8 + 4];
            ull ad[8] = {dup2(a0.x), dup2(a0.y), dup2(a0.z), dup2(a0.w),
                         dup2(a1.x), dup2(a1.y), dup2(a1.z), dup2(a1.w)};
            ull bp[4] = {bb0.x, bb0.y, bb1.x, bb1.y};
#pragma unroll
            for (int mm = 0; mm < 8; mm++)
#pragma unroll
                for (int np = 0; np < 4; np++) fma2(acc[mm][np], ad[mm], bp[np]);
        }
        __syncthreads();
    }
#pragma unroll
    for (int mm = 0; mm < 8; mm++) {
        int m = m0 + ty * 8 + mm;
#pragma unroll
        for (int np = 0; np < 4; np++) {
            float f0, f1;
            unpack2(acc[mm][np], f0, f1);
#pragma unroll
            for (int e = 0; e < 2; e++) {
                float f = e ? f1 : f0;
                int n = n0 + tx * 8 + np * 2 + e;
                if (MODE == 0) {
                    g_c2[(size_t)m * 256 + n] = fast_tanh(f + __ldg(&bias[n]));
                } else if (MODE == 1) {
                    int o = n >> 2, kcv = n & 3;
                    float v = fast_tanh(f + __ldg(&bias[o]));
                    int bb = m >> 10, t = m & 1023;
                    g_c3[((size_t)bb * 4096 + 4 * t + kcv) * 256 + o] = v;
                } else {
                    float v = f + __ldg(&bias[n]);
                    int bb = m >> 12, t = m & 4095;
                    int gate = n >> 8, ch = n & 255;
                    int sl = ch >> 5, loc = (gate << 5) + (ch & 31);
                    g_gx[((size_t)(bb * 8 + sl) * 4096 + t) * 96 + loc] = v;
                }
            }
        }
    }
}

// ============================================================================
// GRU: 16 clusters x 8 CTAs; R12's ordering-free merged-word protocol, but
// transported over raw DSMEM pushes instead of L2:
//  - producer warp0 lane packs (epoch<<32 | h_bits) and st.shared::cluster's
//    it into land[bin][ch] of ALL 8 peers (incl. self). NO mbarrier, NO
//    fence, NO arrive — the word is self-contained.
//  - gather warps 1-8 poll their 32 LOCAL land words (volatile LDS, 29-cyc
//    granularity) until epoch==t+1, then write swizzled h_buf[bin].
//  - two __syncthreads per step, exactly the R12 structure that won.
// Replay safety: land zero-init each launch + exact-epoch match (>=1).
// Exit safety: cluster_sync after the loop (no CTA exits while peers push).
// ============================================================================
__global__ void __cluster_dims__(8, 1, 1) __launch_bounds__(384, 1)
gru_kernel(const float* __restrict__ W_hh, const float* __restrict__ b_hh,
           float* __restrict__ out)
{
    __shared__ __align__(16) float h_buf[2][272];   // 4 chunks of 64 @ stride 68
    __shared__ __align__(16) ull land[2][256];      // merged-word landing zone
    __shared__ float gates_s[96];
    const int tid = threadIdx.x;
    const int s = blockIdx.x & 7;
    const int b = blockIdx.x >> 3;
    const int p = tid >> 2, kc = tid & 3;   // 96 rows x 4 K-chunks of 64
    const int grow = ((p >> 5) << 8) + (s << 5) + (p & 31);  // global gate row
    const int warp = tid >> 5, lane = tid & 31;

    // 64 weights per thread as 32 f32x2 regs
    ull wp[32];
    const ull* Wp = (const ull*)W_hh;
#pragma unroll
    for (int j = 0; j < 32; j++) wp[j] = Wp[grow * 128 + kc * 32 + j];
    for (int i = tid; i < 272; i += 384) h_buf[0][i] = 0.f;
    for (int i = tid; i < 512; i += 384) ((ull*)land)[i] = 0ULL;  // epoch 0

    const size_t gx_base = (size_t)(b * 8 + s) * 4096 * 96;
    float bhr = 0.f, bhz = 0.f, bhn = 0.f, gxr = 0.f, gxz = 0.f, gxn = 0.f;
    float hold = 0.f;
    uint32_t rl[2][8];           // warp0: remote land word addrs (bin, peer)
    uint32_t pollA = 0;          // gather warps: local land word address
    int sidx = 0;                // gather: swizzled smem index for channel c
    if (warp == 0) {
        int ch = (s << 5) + lane;
        bhr = b_hh[ch]; bhz = b_hh[256 + ch]; bhn = b_hh[512 + ch];
        gxr = g_gx[gx_base + lane] + bhr;          // biases folded in
        gxz = g_gx[gx_base + 32 + lane] + bhz;
        gxn = g_gx[gx_base + 64 + lane] + bhn;
        uint32_t l0 = smem_u32(&land[0][ch]);
        uint32_t l1 = smem_u32(&land[1][ch]);
#pragma unroll
        for (int pr = 0; pr < 8; pr++) {
            rl[0][pr] = mapa_u32(l0, pr);
            rl[1][pr] = mapa_u32(l1, pr);
        }
    } else if (warp <= 8) {
        int c = ((warp - 1) << 5) + lane;          // channel this lane gathers
        pollA = smem_u32(&land[0][c]);             // + bin*2048
        sidx = (c >> 6) * 68 + (c & 63);
    }
    __syncthreads();
    cluster_sync_();  // land zero-init visible before any peer push

    for (int t = 0; t < 4096; t++) {
        const int par = t & 1;
        const int bin = par ^ 1;          // landing set carrying h_{t+1}
        const bool last = (t == 4095);

        // ---- f32x2 gemv: row grow, h chunk [64kc, 64kc+64), swizzled ----
        ull accA = 0ULL, accB = 0ULL;
        const ulonglong2* hb = (const ulonglong2*)&h_buf[par][kc * 68];
#pragma unroll
        for (int j = 0; j < 16; j++) {
            ulonglong2 hv = hb[j];
            fma2(accA, wp[2 * j + 0], hv.x);
            fma2(accB, wp[2 * j + 1], hv.y);
        }
        float ax, ay, bx, by;
        unpack2(accA, ax, ay); unpack2(accB, bx, by);
        float r0 = (ax + ay) + (bx + by);
        r0 += __shfl_xor_sync(0xffffffffu, r0, 1);
        r0 += __shfl_xor_sync(0xffffffffu, r0, 2);
        if (kc == 0) gates_s[p] = r0;
        __syncthreads();

        if (warp == 0) {
            // ---- activation for this CTA's 32 channels ----
            float dr = gates_s[lane];
            float dz = gates_s[32 + lane];
            float dn = gates_s[64 + lane];
            float r = fast_sig(gxr + dr);
            float z = fast_sig(gxz + dz);
            float n = fast_tanh(gxn + r * dn);
            float hnew = fmaf(z, hold - n, n);  // (1-z)n + z*h
            hold = hnew;
            if (!last) {
                // push merged word to all 8 peers' landing zones (incl. self)
                ull w = ((ull)(uint32_t)(t + 1) << 32) |
                        (ull)__float_as_uint(hnew);
#pragma unroll
                for (int pr = 0; pr < 8; pr++)
                    st_cluster_b64(rl[bin][pr], w);
            }
            out[((size_t)b * 4096 + t) * 256 + (s << 5) + lane] = hnew;
            // prefetch next step's x-gates (off critical path)
            int tn = last ? t : (t + 1);
            size_t off = gx_base + (size_t)tn * 96;
            gxr = __ldg(&g_gx[off + lane]) + bhr;
            gxz = __ldg(&g_gx[off + 32 + lane]) + bhz;
            gxn = __ldg(&g_gx[off + 64 + lane]) + bhn;
        } else if (warp <= 8 && !last) {
            // ---- gather h_{t+1}: poll LOCAL land word until epoch matches
            const uint32_t wa = pollA + bin * 2048;
            const uint32_t target = (uint32_t)(t + 1);
            ull w = ld_volatile_shared_b64(wa);
            while ((uint32_t)(w >> 32) != target) w = ld_volatile_shared_b64(wa);
            h_buf[bin][sidx] = __uint_as_float((uint32_t)w);
        }
        __syncthreads();
    }
    cluster_sync_();  // no CTA exits while peers may still push to its smem
}

// ============================================================================
extern "C" void kernel_launch(void* const* d_in, const int* in_sizes, int n_in,
                              void* d_out, int out_size)
{
    const float* features = (const float*)d_in[0];
    const float* W1   = (const float*)d_in[1];
    const float* b1   = (const float*)d_in[2];
    const float* W2   = (const float*)d_in[3];
    const float* b2   = (const float*)d_in[4];
    const float* Wt   = (const float*)d_in[5];
    const float* bt   = (const float*)d_in[6];
    const float* W_ih = (const float*)d_in[7];
    const float* W_hh = (const float*)d_in[8];
    const float* b_ih = (const float*)d_in[9];
    const float* b_hh = (const float*)d_in[10];
    float* out = (float*)d_out;

    conv1_kernel<<<dim3(128, 16), 256>>>(features, W1, b1);
    prep_kernel<<<768, 768>>>(W2, W_ih);
    gemm_kernel<0><<<dim3(128, 2), 256>>>(nullptr, b2);
    gemm_kernel<1><<<dim3(128, 8), 256>>>(Wt, bt);
    gemm_kernel<2><<<dim3(512, 6), 256>>>(nullptr, b_ih);
    gru_kernel<<<128, 384>>>(W_hh, b_hh, out);
}

// round 15
// speedup vs baseline: 1.7689x; 1.7689x over previous
#include <cuda_runtime.h>
#include <cstdint>

#define DEV_INLINE __device__ __forceinline__
typedef unsigned long long ull;

// ---------------- scratch (device globals; no allocations allowed) ----------
__device__ float g_c1[16 * 1024 * 256];            // after conv1 + frame grouping
__device__ float g_c2[16 * 1024 * 256];            // after conv2
__device__ float g_c3[16 * 4096 * 256];            // after tconv
__device__ float g_gx[(size_t)16 * 8 * 4096 * 96]; // gates_x, GRU-CTA-sliced layout
__device__ float g_w2t[512 * 256];                 // W2 transposed: [kk][o]
__device__ float g_wihT[256 * 768];                // W_ih transposed: [c][g]
// GRU h exchange: merged (epoch<<32 | value_bits) words, double-buffered
__device__ ull g_hv[2 * 16 * 256];                 // [bin][batch][channel]

// ---------------- packed f32x2 helpers --------------------------------------
DEV_INLINE ull dup2(float x) {
    ull r; asm("mov.b64 %0, {%1, %1};" : "=l"(r) : "f"(x)); return r;
}
DEV_INLINE void fma2(ull& d, ull a, ull b) {
    asm("fma.rn.f32x2 %0, %1, %2, %0;" : "+l"(d) : "l"(a), "l"(b));
}
DEV_INLINE void unpack2(ull v, float& x, float& y) {
    asm("mov.b64 {%0, %1}, %2;" : "=f"(x), "=f"(y) : "l"(v));
}

// ---------------- fast activations (MUFU ex2 + rcp; rel err ~1e-6) ----------
DEV_INLINE float fast_tanh(float x) {
    x = fminf(15.f, fmaxf(-15.f, x));
    float e = __expf(2.f * x);
    return __fdividef(e - 1.f, e + 1.f);
}
DEV_INLINE float fast_sig(float x) {
    x = fminf(30.f, fmaxf(-30.f, x));
    return __fdividef(1.f, 1.f + __expf(-x));
}

// ---------------- relaxed 8B atomics through L2 (no acquire/release) --------
DEV_INLINE ull ld_relaxed_gpu_b64(const ull* p) {
    ull v;
    asm volatile("ld.relaxed.gpu.global.b64 %0, [%1];" : "=l"(v) : "l"(p) : "memory");
    return v;
}
DEV_INLINE void st_relaxed_gpu_b64(ull* p, ull v) {
    asm volatile("st.relaxed.gpu.global.b64 [%0], %1;" :: "l"(p), "l"(v) : "memory");
}
// ---------------- cp.async helpers ------------------------------------------
DEV_INLINE uint32_t smem_u32(const void* p) {
    return (uint32_t)__cvta_generic_to_shared(p);
}
DEV_INLINE void cp_async16(uint32_t saddr, const void* gptr) {
    asm volatile("cp.async.cg.shared.global [%0], [%1], 16;"
                 :: "r"(saddr), "l"(gptr) : "memory");
}
#define CP_COMMIT() asm volatile("cp.async.commit_group;" ::: "memory")
#define CP_WAIT0()  asm volatile("cp.async.wait_group 0;" ::: "memory")

// ============================================================================
// Kernel A: conv1 (k=1 pointwise, 47->64) + tanh + frame grouping (B,1024,256)
// ============================================================================
__global__ __launch_bounds__(256) void conv1_kernel(
    const float* __restrict__ feat, const float* __restrict__ W1,
    const float* __restrict__ b1)
{
    __shared__ float sW[64 * 47];
    __shared__ float sb[64];
    __shared__ float sx[32 * 47];
    const int tid = threadIdx.x;
    const int b = blockIdx.y;
    const int f0 = blockIdx.x * 32;
    for (int i = tid; i < 64 * 47; i += 256) sW[i] = W1[i];
    if (tid < 64) sb[tid] = b1[tid];
    const float* fp = feat + ((size_t)b * 4096 + f0) * 47;
    for (int i = tid; i < 32 * 47; i += 256) sx[i] = fp[i];
    __syncthreads();
#pragma unroll
    for (int r = 0; r < 8; r++) {
        int idx = tid + 256 * r;
        int f = idx >> 6, h = idx & 63;
        float acc = sb[h];
#pragma unroll
        for (int i = 0; i < 47; i++) acc = fmaf(sx[f * 47 + i], sW[h * 47 + i], acc);
        int gf = f0 + f;
        g_c1[((size_t)b * 1024 + (gf >> 2)) * 256 + ((gf & 3) << 6) + h] = fast_tanh(acc);
    }
}

// ============================================================================
// Prep: both weight transposes in ONE kernel.
// ============================================================================
__global__ __launch_bounds__(768) void prep_kernel(
    const float* __restrict__ W2, const float* __restrict__ W_ih)
{
    int blk = blockIdx.x;
    int t = threadIdx.x;
    if (blk < 512) {
        if (t < 256)
            g_w2t[blk * 256 + t] = W2[t * 512 + ((blk & 255) << 1) + (blk >> 8)];
    } else {
        int c = blk - 512;                 // 0..255
        g_wihT[c * 768 + t] = W_ih[t * 256 + c];
    }
}

// ============================================================================
// Pipelined GEMM (128x128 tile, BK=16, double-buffered smem):
//  - B tile via cp.async.cg (LDGSTS, issue-and-forget)
//  - A tile via register staging: LDG for tile k+1 issued BEFORE compute of
//    tile k; transposed store into the other buffer after compute.
//  - ONE __syncthreads per tile; WAR ordered through it.
// MODE 0: conv2 (M=16384,K=512v,N=256)  A=c1 shifted pairs, B=g_w2t -> c2
// MODE 1: tconv (M=16384,K=256,N=1024)  A=c2, B=Wt (native layout)  -> c3
// MODE 2: gates (M=65536,K=256,N=768)   A=c3, B=g_wihT              -> g_gx
// ============================================================================
template <int MODE>
__global__ __launch_bounds__(256) void gemm_kernel(
    const float* __restrict__ Bext, const float* __restrict__ bias)
{
    __shared__ float As[2][16][136];
    __shared__ float Bs[2][16][128];
    const int tid = threadIdx.x;
    const int tx = tid & 15, ty = tid >> 4;
    const int m0 = blockIdx.x * 128;
    const int n0 = blockIdx.y * 128;
    constexpr int K   = (MODE == 0) ? 512 : 256;
    constexpr int NT  = K / 16;
    constexpr int Nld = (MODE == 0) ? 256 : (MODE == 1 ? 1024 : 768);
    const float* Bm = (MODE == 0) ? g_w2t : (MODE == 1 ? Bext : g_wihT);
    const float* Amat = (MODE == 1) ? g_c2 : g_c3;

    // per-thread load coords (2 float4 each for A and B per tile)
    const int arow0 = tid >> 1;                 // A: rows handled (it=0/1)
    const int akq0  = (tid & 1) << 3;           //   [it*? ] see loop below
    (void)arow0; (void)akq0;

    ull acc[8][4];
#pragma unroll
    for (int i = 0; i < 8; i++)
#pragma unroll
        for (int j = 0; j < 4; j++) acc[i][j] = 0ULL;

    float4 av[2];
    // ---- A global load for tile starting at k0 (into regs) ----
    auto loadA = [&](int k0) {
#pragma unroll
        for (int it = 0; it < 2; it++) {
            int idx = tid + it * 256;
            int row = idx >> 2;
            int kq = (idx & 3) << 2;
            int m = m0 + row;
            if (MODE == 0) {
                if (k0 < 256) {
                    if ((m & 1023) != 0)
                        av[it] = *(const float4*)&g_c1[((size_t)m - 1) * 256 + k0 + kq];
                    else
                        av[it] = make_float4(0.f, 0.f, 0.f, 0.f);
                } else {
                    av[it] = *(const float4*)&g_c1[(size_t)m * 256 + (k0 - 256) + kq];
                }
            } else {
                av[it] = *(const float4*)&Amat[(size_t)m * 256 + k0 + kq];
            }
        }
    };
    auto storeA = [&](int buf) {
#pragma unroll
        for (int it = 0; it < 2; it++) {
            int idx = tid + it * 256;
            int row = idx >> 2;
            int kq = (idx & 3) << 2;
            As[buf][kq + 0][row] = av[it].x;
            As[buf][kq + 1][row] = av[it].y;
            As[buf][kq + 2][row] = av[it].z;
            As[buf][kq + 3][row] = av[it].w;
        }
    };
    auto issueB = [&](int k0, int buf) {
#pragma unroll
        for (int it = 0; it < 2; it++) {
            int idx = tid + it * 256;
            int kr = idx >> 5;
            int nq = (idx & 31) << 2;
            cp_async16(smem_u32(&Bs[buf][kr][nq]),
                       &Bm[(size_t)(k0 + kr) * Nld + n0 + nq]);
        }
    };

    // ---- prologue ----
    loadA(0);
    issueB(0, 0);
    CP_COMMIT();
    storeA(0);
    CP_WAIT0();
    __syncthreads();

    for (int kt = 0; kt < NT; kt++) {
        const int cur = kt & 1;
        const int nxt = cur ^ 1;
        if (kt + 1 < NT) {
            loadA((kt + 1) * 16);      // LDG in flight during compute
            issueB((kt + 1) * 16, nxt);
            CP_COMMIT();
        }
        // ---- compute on tile cur ----
#pragma unroll
        for (int kk = 0; kk < 16; kk++) {
            float4 a0 = *(const float4*)&As[cur][kk][ty * 8];
            float4 a1 = *(const float4*)&As[cur][kk][ty * 8 + 4];
            ulonglong2 bb0 = *(const ulonglong2*)&Bs[cur][kk][tx * 8];
            ulonglong2 bb1 = *(const ulonglong2*)&Bs[cur][kk][tx * 8 + 4];
            ull ad[8] = {dup2(a0.x), dup2(a0.y), dup2(a0.z), dup2(a0.w),
                         dup2(a1.x), dup2(a1.y), dup2(a1.z), dup2(a1.w)};
            ull bp[4] = {bb0.x, bb0.y, bb1.x, bb1.y};
#pragma unroll
            for (int mm = 0; mm < 8; mm++)
#pragma unroll
                for (int np = 0; np < 4; np++) fma2(acc[mm][np], ad[mm], bp[np]);
        }
        if (kt + 1 < NT) {
            storeA(nxt);               // regs -> smem (other buffer)
            CP_WAIT0();
            __syncthreads();
        }
    }
    // ---- epilogue ----
#pragma unroll
    for (int mm = 0; mm < 8; mm++) {
        int m = m0 + ty * 8 + mm;
#pragma unroll
        for (int np = 0; np < 4; np++) {
            float f0, f1;
            unpack2(acc[mm][np], f0, f1);
#pragma unroll
            for (int e = 0; e < 2; e++) {
                float f = e ? f1 : f0;
                int n = n0 + tx * 8 + np * 2 + e;
                if (MODE == 0) {
                    g_c2[(size_t)m * 256 + n] = fast_tanh(f + __ldg(&bias[n]));
                } else if (MODE == 1) {
                    int o = n >> 2, kcv = n & 3;
                    float v = fast_tanh(f + __ldg(&bias[o]));
                    int bb = m >> 10, t = m & 1023;
                    g_c3[((size_t)bb * 4096 + 4 * t + kcv) * 256 + o] = v;
                } else {
                    float v = f + __ldg(&bias[n]);
                    int bb = m >> 12, t = m & 4095;
                    int gate = n >> 8, ch = n & 255;
                    int sl = ch >> 5, loc = (gate << 5) + (ch & 31);
                    g_gx[((size_t)(bb * 8 + sl) * 4096 + t) * 96 + loc] = v;
                }
            }
        }
    }
}

// ============================================================================
// GRU: 128 independent CTAs (16 batches x 8 slots) — the R12 WINNING version,
// byte-for-byte, except b_hh folded into the gx prefetch (off critical path).
// Exchange via merged (epoch<<32 | value) b64 words in L2, ld/st.relaxed.gpu.
// ============================================================================
__global__ void __launch_bounds__(384, 1)
gru_kernel(const float* __restrict__ W_hh, const float* __restrict__ b_hh,
           float* __restrict__ out)
{
    __shared__ __align__(16) float h_buf[2][272];   // 4 chunks of 64 @ stride 68
    __shared__ float gates_s[96];
    const int tid = threadIdx.x;
    const int s = blockIdx.x & 7;
    const int b = blockIdx.x >> 3;
    const int p = tid >> 2, kc = tid & 3;   // 96 rows x 4 K-chunks of 64
    const int grow = ((p >> 5) << 8) + (s << 5) + (p & 31);  // global gate row
    const int warp = tid >> 5, lane = tid & 31;

    // 64 weights per thread as 32 f32x2 regs
    ull wp[32];
    const ull* Wp = (const ull*)W_hh;
#pragma unroll
    for (int j = 0; j < 32; j++) wp[j] = Wp[grow * 128 + kc * 32 + j];
    for (int i = tid; i < 272; i += 384) h_buf[0][i] = 0.f;

    const size_t gx_base = (size_t)(b * 8 + s) * 4096 * 96;
    float bhr = 0.f, bhz = 0.f, bhn = 0.f, gxr = 0.f, gxz = 0.f, gxn = 0.f;
    float hold = 0.f;
    ull* pub = nullptr;          // warp0: this lane's publish word (per bin)
    const ull* pollp = nullptr;  // gather warps: this lane's poll word
    int sidx = 0;                // gather: swizzled smem index for channel c
    if (warp == 0) {
        int ch = (s << 5) + lane;
        bhr = b_hh[ch]; bhz = b_hh[256 + ch]; bhn = b_hh[512 + ch];
        gxr = g_gx[gx_base + lane] + bhr;          // biases folded in
        gxz = g_gx[gx_base + 32 + lane] + bhz;
        gxn = g_gx[gx_base + 64 + lane] + bhn;
        pub = &g_hv[(size_t)b * 256 + ch];          // + bin*4096
    } else if (warp <= 8) {
        int c = ((warp - 1) << 5) + lane;           // channel this lane gathers
        pollp = &g_hv[(size_t)b * 256 + c];         // + bin*4096
        sidx = (c >> 6) * 68 + (c & 63);            // swizzled position
    }
    __syncthreads();

    for (int t = 0; t < 4096; t++) {
        const int par = t & 1;
        const int bin = par ^ 1;          // word set carrying h_{t+1}
        const bool last = (t == 4095);

        // ---- f32x2 gemv: row grow, h chunk [64kc, 64kc+64), swizzled ----
        ull accA = 0ULL, accB = 0ULL;
        const ulonglong2* hb = (const ulonglong2*)&h_buf[par][kc * 68];
#pragma unroll
        for (int j = 0; j < 16; j++) {
            ulonglong2 hv = hb[j];
            fma2(accA, wp[2 * j + 0], hv.x);
            fma2(accB, wp[2 * j + 1], hv.y);
        }
        float ax, ay, bx, by;
        unpack2(accA, ax, ay); unpack2(accB, bx, by);
        float r0 = (ax + ay) + (bx + by);
        r0 += __shfl_xor_sync(0xffffffffu, r0, 1);
        r0 += __shfl_xor_sync(0xffffffffu, r0, 2);
        if (kc == 0) gates_s[p] = r0;
        __syncthreads();

        if (warp == 0) {
            // ---- activation for this CTA's 32 channels ----
            float dr = gates_s[lane];
            float dz = gates_s[32 + lane];
            float dn = gates_s[64 + lane];
            float r = fast_sig(gxr + dr);
            float z = fast_sig(gxz + dz);
            float n = fast_tanh(gxn + r * dn);
            float hnew = fmaf(z, hold - n, n);  // (1-z)n + z*h
            hold = hnew;
            if (!last) {
                ull w = ((ull)(uint32_t)(t + 1) << 32) |
                        (ull)__float_as_uint(hnew);
                st_relaxed_gpu_b64(pub + bin * 4096, w);
            }
            out[((size_t)b * 4096 + t) * 256 + (s << 5) + lane] = hnew;
            // prefetch next step's x-gates (off critical path)
            int tn = last ? t : (t + 1);
            size_t off = gx_base + (size_t)tn * 96;
            gxr = __ldg(&g_gx[off + lane]) + bhr;
            gxz = __ldg(&g_gx[off + 32 + lane]) + bhz;
            gxn = __ldg(&g_gx[off + 64 + lane]) + bhn;
        } else if (warp <= 8 && !last) {
            // ---- gather h_{t+1}: poll own word until epoch matches ----
            const ull* wptr = pollp + bin * 4096;
            const uint32_t target = (uint32_t)(t + 1);
            ull w = ld_relaxed_gpu_b64(wptr);
            while ((uint32_t)(w >> 32) != target) w = ld_relaxed_gpu_b64(wptr);
            h_buf[bin][sidx] = __uint_as_float((uint32_t)w);
        }
        __syncthreads();
    }
}

// ============================================================================
extern "C" void kernel_launch(void* const* d_in, const int* in_sizes, int n_in,
                              void* d_out, int out_size)
{
    const float* features = (const float*)d_in[0];
    const float* W1   = (const float*)d_in[1];
    const float* b1   = (const float*)d_in[2];
    const float* W2   = (const float*)d_in[3];
    const float* b2   = (const float*)d_in[4];
    const float* Wt   = (const float*)d_in[5];
    const float* bt   = (const float*)d_in[6];
    const float* W_ih = (const float*)d_in[7];
    const float* W_hh = (const float*)d_in[8];
    const float* b_ih = (const float*)d_in[9];
    const float* b_hh = (const float*)d_in[10];
    float* out = (float*)d_out;

    conv1_kernel<<<dim3(128, 16), 256>>>(features, W1, b1);
    prep_kernel<<<768, 768>>>(W2, W_ih);
    gemm_kernel<0><<<dim3(128, 2), 256>>>(nullptr, b2);
    gemm_kernel<1><<<dim3(128, 8), 256>>>(Wt, bt);
    gemm_kernel<2><<<dim3(512, 6), 256>>>(nullptr, b_ih);
    gru_kernel<<<128, 384>>>(W_hh, b_hh, out);
}

// round 16
// speedup vs baseline: 1.9813x; 1.1201x over previous
#include <cuda_runtime.h>
#include <cstdint>

#define DEV_INLINE __device__ __forceinline__
typedef unsigned long long ull;

// ---------------- scratch (device globals; no allocations allowed) ----------
__device__ float g_c1[16 * 1024 * 256];            // after conv1 + frame grouping
__device__ float g_c2[16 * 1024 * 256];            // after conv2
__device__ float g_c3[16 * 4096 * 256];            // after tconv
__device__ float g_gx[(size_t)16 * 8 * 4096 * 96]; // gates_x, GRU-CTA-sliced layout
__device__ float g_w2t[512 * 256];                 // W2 transposed: [kk][o]
__device__ float g_wihT[256 * 768];                // W_ih transposed: [c][g]
// GRU h exchange: merged (epoch<<32 | value_bits) words, double-buffered
__device__ ull g_hv[2 * 16 * 256];                 // [bin][batch][channel]

// ---------------- packed f32x2 helpers --------------------------------------
DEV_INLINE ull dup2(float x) {
    ull r; asm("mov.b64 %0, {%1, %1};" : "=l"(r) : "f"(x)); return r;
}
DEV_INLINE void fma2(ull& d, ull a, ull b) {
    asm("fma.rn.f32x2 %0, %1, %2, %0;" : "+l"(d) : "l"(a), "l"(b));
}
DEV_INLINE void unpack2(ull v, float& x, float& y) {
    asm("mov.b64 {%0, %1}, %2;" : "=f"(x), "=f"(y) : "l"(v));
}

// ---------------- fast activations (MUFU ex2 + rcp; rel err ~1e-6) ----------
DEV_INLINE float fast_tanh(float x) {
    x = fminf(15.f, fmaxf(-15.f, x));
    float e = __expf(2.f * x);
    return __fdividef(e - 1.f, e + 1.f);
}
DEV_INLINE float fast_sig(float x) {
    x = fminf(30.f, fmaxf(-30.f, x));
    return __fdividef(1.f, 1.f + __expf(-x));
}

// ---------------- relaxed 8B atomics through L2 (no acquire/release) --------
DEV_INLINE ull ld_relaxed_gpu_b64(const ull* p) {
    ull v;
    asm volatile("ld.relaxed.gpu.global.b64 %0, [%1];" : "=l"(v) : "l"(p) : "memory");
    return v;
}
DEV_INLINE void st_relaxed_gpu_b64(ull* p, ull v) {
    asm volatile("st.relaxed.gpu.global.b64 [%0], %1;" :: "l"(p), "l"(v) : "memory");
}
// ---------------- cp.async helpers ------------------------------------------
DEV_INLINE uint32_t smem_u32(const void* p) {
    return (uint32_t)__cvta_generic_to_shared(p);
}
DEV_INLINE void cp_async16(uint32_t saddr, const void* gptr) {
    asm volatile("cp.async.cg.shared.global [%0], [%1], 16;"
                 :: "r"(saddr), "l"(gptr) : "memory");
}
#define CP_COMMIT() asm volatile("cp.async.commit_group;" ::: "memory")
#define CP_WAIT0()  asm volatile("cp.async.wait_group 0;" ::: "memory")

// ============================================================================
// Kernel A: conv1 (k=1 pointwise, 47->64) + tanh + frame grouping (B,1024,256)
// ============================================================================
__global__ __launch_bounds__(256) void conv1_kernel(
    const float* __restrict__ feat, const float* __restrict__ W1,
    const float* __restrict__ b1)
{
    __shared__ float sW[64 * 47];
    __shared__ float sb[64];
    __shared__ float sx[32 * 47];
    const int tid = threadIdx.x;
    const int b = blockIdx.y;
    const int f0 = blockIdx.x * 32;
    for (int i = tid; i < 64 * 47; i += 256) sW[i] = W1[i];
    if (tid < 64) sb[tid] = b1[tid];
    const float* fp = feat + ((size_t)b * 4096 + f0) * 47;
    for (int i = tid; i < 32 * 47; i += 256) sx[i] = fp[i];
    __syncthreads();
#pragma unroll
    for (int r = 0; r < 8; r++) {
        int idx = tid + 256 * r;
        int f = idx >> 6, h = idx & 63;
        float acc = sb[h];
#pragma unroll
        for (int i = 0; i < 47; i++) acc = fmaf(sx[f * 47 + i], sW[h * 47 + i], acc);
        int gf = f0 + f;
        g_c1[((size_t)b * 1024 + (gf >> 2)) * 256 + ((gf & 3) << 6) + h] = fast_tanh(acc);
    }
}

// ============================================================================
// Prep: both weight transposes in ONE kernel.
// ============================================================================
__global__ __launch_bounds__(768) void prep_kernel(
    const float* __restrict__ W2, const float* __restrict__ W_ih)
{
    int blk = blockIdx.x;
    int t = threadIdx.x;
    if (blk < 512) {
        if (t < 256)
            g_w2t[blk * 256 + t] = W2[t * 512 + ((blk & 255) << 1) + (blk >> 8)];
    } else {
        int c = blk - 512;                 // 0..255
        g_wihT[c * 768 + t] = W_ih[t * 256 + c];
    }
}

// ============================================================================
// Pipelined GEMM (128x128 tile, BK=16, double-buffered smem):
//  - B tile via cp.async.cg; A tile via register staging (LDG one tile early)
//  - ONE __syncthreads per tile.
// ============================================================================
template <int MODE>
__global__ __launch_bounds__(256) void gemm_kernel(
    const float* __restrict__ Bext, const float* __restrict__ bias)
{
    __shared__ float As[2][16][136];
    __shared__ float Bs[2][16][128];
    const int tid = threadIdx.x;
    const int tx = tid & 15, ty = tid >> 4;
    const int m0 = blockIdx.x * 128;
    const int n0 = blockIdx.y * 128;
    constexpr int K   = (MODE == 0) ? 512 : 256;
    constexpr int NT  = K / 16;
    constexpr int Nld = (MODE == 0) ? 256 : (MODE == 1 ? 1024 : 768);
    const float* Bm = (MODE == 0) ? g_w2t : (MODE == 1 ? Bext : g_wihT);
    const float* Amat = (MODE == 1) ? g_c2 : g_c3;

    ull acc[8][4];
#pragma unroll
    for (int i = 0; i < 8; i++)
#pragma unroll
        for (int j = 0; j < 4; j++) acc[i][j] = 0ULL;

    float4 av[2];
    auto loadA = [&](int k0) {
#pragma unroll
        for (int it = 0; it < 2; it++) {
            int idx = tid + it * 256;
            int row = idx >> 2;
            int kq = (idx & 3) << 2;
            int m = m0 + row;
            if (MODE == 0) {
                if (k0 < 256) {
                    if ((m & 1023) != 0)
                        av[it] = *(const float4*)&g_c1[((size_t)m - 1) * 256 + k0 + kq];
                    else
                        av[it] = make_float4(0.f, 0.f, 0.f, 0.f);
                } else {
                    av[it] = *(const float4*)&g_c1[(size_t)m * 256 + (k0 - 256) + kq];
                }
            } else {
                av[it] = *(const float4*)&Amat[(size_t)m * 256 + k0 + kq];
            }
        }
    };
    auto storeA = [&](int buf) {
#pragma unroll
        for (int it = 0; it < 2; it++) {
            int idx = tid + it * 256;
            int row = idx >> 2;
            int kq = (idx & 3) << 2;
            As[buf][kq + 0][row] = av[it].x;
            As[buf][kq + 1][row] = av[it].y;
            As[buf][kq + 2][row] = av[it].z;
            As[buf][kq + 3][row] = av[it].w;
        }
    };
    auto issueB = [&](int k0, int buf) {
#pragma unroll
        for (int it = 0; it < 2; it++) {
            int idx = tid + it * 256;
            int kr = idx >> 5;
            int nq = (idx & 31) << 2;
            cp_async16(smem_u32(&Bs[buf][kr][nq]),
                       &Bm[(size_t)(k0 + kr) * Nld + n0 + nq]);
        }
    };

    loadA(0);
    issueB(0, 0);
    CP_COMMIT();
    storeA(0);
    CP_WAIT0();
    __syncthreads();

    for (int kt = 0; kt < NT; kt++) {
        const int cur = kt & 1;
        const int nxt = cur ^ 1;
        if (kt + 1 < NT) {
            loadA((kt + 1) * 16);
            issueB((kt + 1) * 16, nxt);
            CP_COMMIT();
        }
#pragma unroll
        for (int kk = 0; kk < 16; kk++) {
            float4 a0 = *(const float4*)&As[cur][kk][ty * 8];
            float4 a1 = *(const float4*)&As[cur][kk][ty * 8 + 4];
            ulonglong2 bb0 = *(const ulonglong2*)&Bs[cur][kk][tx * 8];
            ulonglong2 bb1 = *(const ulonglong2*)&Bs[cur][kk][tx * 8 + 4];
            ull ad[8] = {dup2(a0.x), dup2(a0.y), dup2(a0.z), dup2(a0.w),
                         dup2(a1.x), dup2(a1.y), dup2(a1.z), dup2(a1.w)};
            ull bp[4] = {bb0.x, bb0.y, bb1.x, bb1.y};
#pragma unroll
            for (int mm = 0; mm < 8; mm++)
#pragma unroll
                for (int np = 0; np < 4; np++) fma2(acc[mm][np], ad[mm], bp[np]);
        }
        if (kt + 1 < NT) {
            storeA(nxt);
            CP_WAIT0();
            __syncthreads();
        }
    }
#pragma unroll
    for (int mm = 0; mm < 8; mm++) {
        int m = m0 + ty * 8 + mm;
#pragma unroll
        for (int np = 0; np < 4; np++) {
            float f0, f1;
            unpack2(acc[mm][np], f0, f1);
#pragma unroll
            for (int e = 0; e < 2; e++) {
                float f = e ? f1 : f0;
                int n = n0 + tx * 8 + np * 2 + e;
                if (MODE == 0) {
                    g_c2[(size_t)m * 256 + n] = fast_tanh(f + __ldg(&bias[n]));
                } else if (MODE == 1) {
                    int o = n >> 2, kcv = n & 3;
                    float v = fast_tanh(f + __ldg(&bias[o]));
                    int bb = m >> 10, t = m & 1023;
                    g_c3[((size_t)bb * 4096 + 4 * t + kcv) * 256 + o] = v;
                } else {
                    float v = f + __ldg(&bias[n]);
                    int bb = m >> 12, t = m & 4095;
                    int gate = n >> 8, ch = n & 255;
                    int sl = ch >> 5, loc = (gate << 5) + (ch & 31);
                    g_gx[((size_t)(bb * 8 + sl) * 4096 + t) * 96 + loc] = v;
                }
            }
        }
    }
}

// ============================================================================
// GRU: 128 independent CTAs (16 batches x 8 slots) — R12 WINNING structure,
// byte-for-byte (NO bias folding: the prefetch LDG must stay unconsumed so
// warp0 reaches the barrier without waiting on memory). Only change: the
// gather poll issues TWO independent loads per iteration (halves detection
// granularity of the serial load->compare->branch chain).
// ============================================================================
__global__ void __launch_bounds__(384, 1)
gru_kernel(const float* __restrict__ W_hh, const float* __restrict__ b_hh,
           float* __restrict__ out)
{
    __shared__ __align__(16) float h_buf[2][272];   // 4 chunks of 64 @ stride 68
    __shared__ float gates_s[96];
    const int tid = threadIdx.x;
    const int s = blockIdx.x & 7;
    const int b = blockIdx.x >> 3;
    const int p = tid >> 2, kc = tid & 3;   // 96 rows x 4 K-chunks of 64
    const int grow = ((p >> 5) << 8) + (s << 5) + (p & 31);  // global gate row
    const int warp = tid >> 5, lane = tid & 31;

    // 64 weights per thread as 32 f32x2 regs
    ull wp[32];
    const ull* Wp = (const ull*)W_hh;
#pragma unroll
    for (int j = 0; j < 32; j++) wp[j] = Wp[grow * 128 + kc * 32 + j];
    for (int i = tid; i < 272; i += 384) h_buf[0][i] = 0.f;

    const size_t gx_base = (size_t)(b * 8 + s) * 4096 * 96;
    float bhr = 0.f, bhz = 0.f, bhn = 0.f, gxr = 0.f, gxz = 0.f, gxn = 0.f;
    float hold = 0.f;
    ull* pub = nullptr;          // warp0: this lane's publish word (per bin)
    const ull* pollp = nullptr;  // gather warps: this lane's poll word
    int sidx = 0;                // gather: swizzled smem index for channel c
    if (warp == 0) {
        int ch = (s << 5) + lane;
        bhr = b_hh[ch]; bhz = b_hh[256 + ch]; bhn = b_hh[512 + ch];
        gxr = g_gx[gx_base + lane];
        gxz = g_gx[gx_base + 32 + lane];
        gxn = g_gx[gx_base + 64 + lane];
        pub = &g_hv[(size_t)b * 256 + ch];          // + bin*4096
    } else if (warp <= 8) {
        int c = ((warp - 1) << 5) + lane;           // channel this lane gathers
        pollp = &g_hv[(size_t)b * 256 + c];         // + bin*4096
        sidx = (c >> 6) * 68 + (c & 63);            // swizzled position
    }
    __syncthreads();

    for (int t = 0; t < 4096; t++) {
        const int par = t & 1;
        const int bin = par ^ 1;          // word set carrying h_{t+1}
        const bool last = (t == 4095);

        // ---- f32x2 gemv: row grow, h chunk [64kc, 64kc+64), swizzled ----
        ull accA = 0ULL, accB = 0ULL;
        const ulonglong2* hb = (const ulonglong2*)&h_buf[par][kc * 68];
#pragma unroll
        for (int j = 0; j < 16; j++) {
            ulonglong2 hv = hb[j];
            fma2(accA, wp[2 * j + 0], hv.x);
            fma2(accB, wp[2 * j + 1], hv.y);
        }
        float ax, ay, bx, by;
        unpack2(accA, ax, ay); unpack2(accB, bx, by);
        float r0 = (ax + ay) + (bx + by);
        r0 += __shfl_xor_sync(0xffffffffu, r0, 1);
        r0 += __shfl_xor_sync(0xffffffffu, r0, 2);
        if (kc == 0) gates_s[p] = r0;
        __syncthreads();

        if (warp == 0) {
            // ---- activation for this CTA's 32 channels ----
            float dr = gates_s[lane] + bhr;
            float dz = gates_s[32 + lane] + bhz;
            float dn = gates_s[64 + lane] + bhn;
            float r = fast_sig(gxr + dr);
            float z = fast_sig(gxz + dz);
            float n = fast_tanh(gxn + r * dn);
            float hnew = fmaf(z, hold - n, n);  // (1-z)n + z*h
            hold = hnew;
            if (!last) {
                ull w = ((ull)(uint32_t)(t + 1) << 32) |
                        (ull)__float_as_uint(hnew);
                st_relaxed_gpu_b64(pub + bin * 4096, w);
            }
            out[((size_t)b * 4096 + t) * 256 + (s << 5) + lane] = hnew;
            // prefetch next step's x-gates (bare LDG: scoreboard-deferred,
            // consumed only at next step's activation)
            int tn = last ? t : (t + 1);
            size_t off = gx_base + (size_t)tn * 96;
            gxr = __ldg(&g_gx[off + lane]);
            gxz = __ldg(&g_gx[off + 32 + lane]);
            gxn = __ldg(&g_gx[off + 64 + lane]);
        } else if (warp <= 8 && !last) {
            // ---- gather h_{t+1}: dual-load poll (half-RT sampling) ----
            const ull* wptr = pollp + bin * 4096;
            const uint32_t target = (uint32_t)(t + 1);
            ull w;
            for (;;) {
                ull w0 = ld_relaxed_gpu_b64(wptr);
                ull w1 = ld_relaxed_gpu_b64(wptr);
                if ((uint32_t)(w0 >> 32) == target) { w = w0; break; }
                if ((uint32_t)(w1 >> 32) == target) { w = w1; break; }
            }
            h_buf[bin][sidx] = __uint_as_float((uint32_t)w);
        }
        __syncthreads();
    }
}

// ============================================================================
extern "C" void kernel_launch(void* const* d_in, const int* in_sizes, int n_in,
                              void* d_out, int out_size)
{
    const float* features = (const float*)d_in[0];
    const float* W1   = (const float*)d_in[1];
    const float* b1   = (const float*)d_in[2];
    const float* W2   = (const float*)d_in[3];
    const float* b2   = (const float*)d_in[4];
    const float* Wt   = (const float*)d_in[5];
    const float* bt   = (const float*)d_in[6];
    const float* W_ih = (const float*)d_in[7];
    const float* W_hh = (const float*)d_in[8];
    const float* b_ih = (const float*)d_in[9];
    const float* b_hh = (const float*)d_in[10];
    float* out = (float*)d_out;

    conv1_kernel<<<dim3(128, 16), 256>>>(features, W1, b1);
    prep_kernel<<<768, 768>>>(W2, W_ih);
    gemm_kernel<0><<<dim3(128, 2), 256>>>(nullptr, b2);
    gemm_kernel<1><<<dim3(128, 8), 256>>>(Wt, bt);
    gemm_kernel<2><<<dim3(512, 6), 256>>>(nullptr, b_ih);
    gru_kernel<<<128, 384>>>(W_hh, b_hh, out);
}